// round 2
// baseline (speedup 1.0000x reference)
#include <cuda_runtime.h>

#define BB 8
#define HH 512
#define WW 512
#define HW (HH * WW)
#define TX 32
#define TY 16

// Scratch: gray planes for pred and target (8 MB each), plus mismatch counter.
__device__ float g_gp[BB * HW];
__device__ float g_gt[BB * HW];
__device__ unsigned int g_cnt;

__global__ void gray_kernel(const float* __restrict__ pred,
                            const float* __restrict__ tgt) {
    int i = blockIdx.x * blockDim.x + threadIdx.x;
    if (i == 0) g_cnt = 0u;
    const int total = BB * HW;
    const int stride = gridDim.x * blockDim.x;
    for (; i < total; i += stride) {
        int b = i / HW;
        int hw = i - b * HW;
        const float* p = pred + (size_t)b * 3 * HW + hw;
        const float* t = tgt  + (size_t)b * 3 * HW + hw;
        g_gp[i] = fmaf(0.299f, p[0], fmaf(0.587f, p[HW], 0.114f * p[2 * HW]));
        g_gt[i] = fmaf(0.299f, t[0], fmaf(0.587f, t[HW], 0.114f * t[2 * HW]));
    }
}

__global__ void census_kernel() {
    __shared__ float sp[TY + 6][TX + 6];
    __shared__ float st[TY + 6][TX + 6];
    __shared__ int   wsum[(TX * TY) / 32];

    const int b  = blockIdx.z;
    const int x0 = blockIdx.x * TX;
    const int y0 = blockIdx.y * TY;
    const float* __restrict__ gp = g_gp + b * HW;
    const float* __restrict__ gt = g_gt + b * HW;

    const int tid = threadIdx.y * TX + threadIdx.x;

    // Cooperative halo load with reflect indexing (jnp 'reflect': no edge repeat)
    for (int idx = tid; idx < (TY + 6) * (TX + 6); idx += TX * TY) {
        int ly = idx / (TX + 6);
        int lx = idx - ly * (TX + 6);
        int gy = y0 + ly - 3;
        if (gy < 0) gy = -gy; else if (gy >= HH) gy = 2 * HH - 2 - gy;
        int gx = x0 + lx - 3;
        if (gx < 0) gx = -gx; else if (gx >= WW) gx = 2 * WW - 2 - gx;
        sp[ly][lx] = gp[gy * WW + gx];
        st[ly][lx] = gt[gy * WW + gx];
    }
    __syncthreads();

    const int tx = threadIdx.x, ty = threadIdx.y;
    const float cp = sp[ty + 3][tx + 3];
    const float ct = st[ty + 3][tx + 3];

    int cnt = 0;
#pragma unroll
    for (int i = 0; i < 7; i++) {
#pragma unroll
        for (int j = 0; j < 7; j++) {
            if (i == 3 && j == 3) continue;
            bool bp = cp > sp[ty + i][tx + j];
            bool bt = ct > st[ty + i][tx + j];
            cnt += (bp != bt) ? 1 : 0;
        }
    }

    // Warp reduce
#pragma unroll
    for (int o = 16; o > 0; o >>= 1)
        cnt += __shfl_down_sync(0xffffffffu, cnt, o);
    if ((tid & 31) == 0) wsum[tid >> 5] = cnt;
    __syncthreads();

    if (tid < (TX * TY) / 32) {
        int v = wsum[tid];
#pragma unroll
        for (int o = (TX * TY) / 64; o > 0; o >>= 1)
            v += __shfl_down_sync(0xffffu, v, o);
        if (tid == 0) atomicAdd(&g_cnt, (unsigned int)v);
    }
}

__global__ void finalize_kernel(float* __restrict__ out) {
    if (threadIdx.x == 0 && blockIdx.x == 0) {
        const double denom = 48.0 * (double)BB * (double)HW; // 100663296
        out[0] = (float)((double)g_cnt / denom);
    }
}

extern "C" void kernel_launch(void* const* d_in, const int* in_sizes, int n_in,
                              void* d_out, int out_size) {
    const float* pred = (const float*)d_in[0];
    const float* tgt  = (const float*)d_in[1];
    float* out = (float*)d_out;

    (void)in_sizes; (void)n_in; (void)out_size;

    // Gray conversion: 2M output pixels per image
    int threads = 256;
    int blocks = 4096; // grid-stride over 2,097,152 pixels
    gray_kernel<<<blocks, threads>>>(pred, tgt);

    dim3 bdim(TX, TY);
    dim3 gdim(WW / TX, HH / TY, BB);
    census_kernel<<<gdim, bdim>>>();

    finalize_kernel<<<1, 32>>>(out);
}

// round 3
// speedup vs baseline: 1.4759x; 1.4759x over previous
#include <cuda_runtime.h>

#define BB 8
#define HH 512
#define WW 512
#define HW (HH * WW)

#define TX 32          // tile width (= warp width)
#define PY 8           // outputs per thread (vertical)
#define TYW 4          // thread rows per block
#define TILE_H (PY * TYW)   // 32
#define SW (TX + 6)    // 38
#define SH (TILE_H + 6) // 38
#define NBLOCKS ((WW / TX) * (HH / TILE_H) * BB)  // 16*16*8 = 2048

__device__ unsigned int g_partials[NBLOCKS];

__global__ __launch_bounds__(TX * TYW)
void census_fused(const float* __restrict__ pred, const float* __restrict__ tgt) {
    __shared__ float sp[SH][SW];
    __shared__ float st[SH][SW];
    __shared__ int wsum[TYW];

    const int b  = blockIdx.z;
    const int x0 = blockIdx.x * TX;
    const int y0 = blockIdx.y * TILE_H;
    const int tid = threadIdx.y * TX + threadIdx.x;

    const float* __restrict__ pb = pred + (size_t)b * 3 * HW;
    const float* __restrict__ tb = tgt  + (size_t)b * 3 * HW;

    // Cooperative halo load + fused RGB->gray (reflect padding, no edge repeat)
    for (int idx = tid; idx < SH * SW; idx += TX * TYW) {
        int ly = idx / SW;
        int lx = idx - ly * SW;
        int gy = y0 + ly - 3;
        gy = (gy < 0) ? -gy : ((gy >= HH) ? 2 * HH - 2 - gy : gy);
        int gx = x0 + lx - 3;
        gx = (gx < 0) ? -gx : ((gx >= WW) ? 2 * WW - 2 - gx : gx);
        int off = gy * WW + gx;
        float r = pb[off], g = pb[HW + off], bl = pb[2 * HW + off];
        sp[ly][lx] = fmaf(0.299f, r, fmaf(0.587f, g, 0.114f * bl));
        r = tb[off]; g = tb[HW + off]; bl = tb[2 * HW + off];
        st[ly][lx] = fmaf(0.299f, r, fmaf(0.587f, g, 0.114f * bl));
    }
    __syncthreads();

    const int tx   = threadIdx.x;
    const int base = threadIdx.y * PY;   // first center row (tile-relative)

    float cp[PY], ct[PY];
#pragma unroll
    for (int k = 0; k < PY; k++) {
        cp[k] = sp[base + k + 3][tx + 3];
        ct[k] = st[base + k + 3][tx + 3];
    }

    int cnt = 0;
#pragma unroll
    for (int r = 0; r < PY + 6; r++) {
        // Load this window row once into registers, reuse for up to 7 centers
        float vp[7], vt[7];
#pragma unroll
        for (int j = 0; j < 7; j++) {
            vp[j] = sp[base + r][tx + j];
            vt[j] = st[base + r][tx + j];
        }
#pragma unroll
        for (int k = 0; k < PY; k++) {
            if (r < k || r > k + 6) continue;   // compile-time pruned
            const int i = r - k;
#pragma unroll
            for (int j = 0; j < 7; j++) {
                if (i == 3 && j == 3) continue; // center excluded
                bool bp = cp[k] > vp[j];
                bool bt = ct[k] > vt[j];
                cnt += (bp != bt) ? 1 : 0;
            }
        }
    }

    // Block reduction -> per-block partial (no global zeroing needed)
#pragma unroll
    for (int o = 16; o > 0; o >>= 1)
        cnt += __shfl_down_sync(0xffffffffu, cnt, o);
    if (tx == 0) wsum[threadIdx.y] = cnt;
    __syncthreads();
    if (tid == 0) {
        int v = wsum[0] + wsum[1] + wsum[2] + wsum[3];
        int bid = (blockIdx.z * gridDim.y + blockIdx.y) * gridDim.x + blockIdx.x;
        g_partials[bid] = (unsigned int)v;
    }
}

__global__ void finalize_kernel(float* __restrict__ out) {
    __shared__ unsigned int ssum[32];
    int t = threadIdx.x;   // 1024 threads
    unsigned int v = g_partials[t] + g_partials[t + 1024];
#pragma unroll
    for (int o = 16; o > 0; o >>= 1)
        v += __shfl_down_sync(0xffffffffu, v, o);
    if ((t & 31) == 0) ssum[t >> 5] = v;
    __syncthreads();
    if (t < 32) {
        unsigned int s = ssum[t];
#pragma unroll
        for (int o = 16; o > 0; o >>= 1)
            s += __shfl_down_sync(0xffffffffu, s, o);
        if (t == 0) {
            const double denom = 48.0 * (double)BB * (double)HW; // 100663296
            out[0] = (float)((double)s / denom);
        }
    }
}

extern "C" void kernel_launch(void* const* d_in, const int* in_sizes, int n_in,
                              void* d_out, int out_size) {
    const float* pred = (const float*)d_in[0];
    const float* tgt  = (const float*)d_in[1];
    float* out = (float*)d_out;
    (void)in_sizes; (void)n_in; (void)out_size;

    dim3 bdim(TX, TYW);
    dim3 gdim(WW / TX, HH / TILE_H, BB);
    census_fused<<<gdim, bdim>>>(pred, tgt);
    finalize_kernel<<<1, 1024>>>(out);
}